// round 15
// baseline (speedup 1.0000x reference)
#include <cuda_runtime.h>
#include <cuda_fp16.h>
#include <math.h>
#include <stdint.h>

#define NTOK 16384
#define HD 768
#define FF 3072
#define NE 4
#define NX1 (FF / 128)     // 24 layer-1 col blocks
#define NX2 (HD / 128)     // 6  layer-2 col blocks
#define MAXB (NTOK / 128)  // 128 max row blocks per expert
#define NZT  (NTOK / 128)  // 128 zero-LN tiles
#define NW2 48             // W2 conversion strips in the queue head
#define QHEAD (NW2 + NZT)  // 176
#define GRID_PERSIST 304

// ---------------- device scratch (no allocations allowed) ----------------
__device__ int g_counts[NE];
__device__ int g_idx[NE * NTOK];
__device__ int g_yoff[NE + 1];
__device__ int g_e1;       // end of layer-1 range
__device__ int g_e2;       // end of layer-2 range
__device__ int g_total;
__device__ int g_tile;
__device__ int g_cv2;      // W2 conversion strips done (target NW2)
__device__ int g_done[NE * MAXB];
__device__ int g_done2[NE * MAXB];
__device__ __half g_xh[(size_t)NTOK * HD];
__device__ __half g_W1h[(size_t)NE * FF * HD];   // [e][n(FF)][k(HD)] fp16
__device__ __half g_W2h[(size_t)NE * HD * FF];   // [e][n(HD)][k(FF)] fp16
__device__ __half g_Hh[(size_t)NE * NTOK * FF];
__device__ float g_Y[(size_t)NE * NTOK * HD];

// ---------------- small kernels ----------------
__global__ void k_zero() {
    if (threadIdx.x < NE) g_counts[threadIdx.x] = 0;
}

__global__ void k_build(const int* __restrict__ ts) {
    int t = blockIdx.x * blockDim.x + threadIdx.x;
    if (t < NTOK) {
        int e = ts[t];
        if (e > 0) {
            int s = atomicAdd(&g_counts[e - 1], 1);
            g_idx[(e - 1) * NTOK + s] = t;
        }
    }
}

__global__ void k_prep() {
    __shared__ int nyb[NE];
    int t = threadIdx.x;
    if (t < NE) nyb[t] = (g_counts[t] + 127) >> 7;
    __syncthreads();
    if (t == 0) {
        int off = 0;
        for (int e = 0; e < NE; e++) { g_yoff[e] = off; off += nyb[e]; }
        g_yoff[NE] = off;
        g_e1 = QHEAD + off * NX1;
        g_e2 = QHEAD + off * (NX1 + NX2);
        g_total = QHEAD + off * (NX1 + NX2 + 1);
        g_tile = 0;
        g_cv2 = 0;
    }
    for (int i = t; i < NE * MAXB; i += blockDim.x) {
        g_done[i] = 0;
        g_done2[i] = 0;
    }
}

// ---------------- standalone conversion: X + W1 only ----------------
// blocks [0, 6144):           x fp32 -> fp16 (8 elems/thread)
// blocks [6144, 6144+2304):   W1 transpose+convert (64x64 tiles)
#define NBX 6144
#define NBW1 2304

__device__ __forceinline__ void convW_body(const float* __restrict__ W, __half* O,
                                           int K, int N, int e, int nb, int kb,
                                           float (*tile)[65]) {
    const int tx = threadIdx.x & 63;
    const int ty = threadIdx.x >> 6;
    const float* src = W + ((size_t)e * K + kb) * N + nb;
    #pragma unroll
    for (int j = 0; j < 16; j++) {
        int r = ty + j * 4;
        tile[r][tx] = src[(size_t)r * N + tx];
    }
    __syncthreads();
    __half* dst = O + ((size_t)e * N + nb) * K + kb;
    #pragma unroll
    for (int j = 0; j < 16; j++) {
        int rr = ty + j * 4;
        dst[(size_t)rr * K + tx] = __float2half(tile[tx][rr]);
    }
    __syncthreads();
}

__global__ void __launch_bounds__(256) k_conv(const float* __restrict__ x,
                                              const float* __restrict__ W1) {
    __shared__ float tile[64][65];
    const int bid = blockIdx.x;
    if (bid < NBX) {
        size_t i = ((size_t)bid * 256 + threadIdx.x) * 8;
        float4 a = *(const float4*)(x + i);
        float4 b = *(const float4*)(x + i + 4);
        __half2 h0 = __floats2half2_rn(a.x, a.y);
        __half2 h1 = __floats2half2_rn(a.z, a.w);
        __half2 h2 = __floats2half2_rn(b.x, b.y);
        __half2 h3 = __floats2half2_rn(b.z, b.w);
        uint4 v;
        v.x = *(uint32_t*)&h0;
        v.y = *(uint32_t*)&h1;
        v.z = *(uint32_t*)&h2;
        v.w = *(uint32_t*)&h3;
        *(uint4*)(g_xh + i) = v;
    } else {
        int b = bid - NBX;                    // W1: K=HD, N=FF; tiles 48 x 12
        int xb = b % (FF / 64);
        int yb = (b / (FF / 64)) % (HD / 64);
        int e = b / ((FF / 64) * (HD / 64));
        convW_body(W1, g_W1h, HD, FF, e, xb * 64, yb * 64, tile);
    }
}

// ---------------- persistent fused kernel: W2conv + GEMM1 + GEMM2 + LN ----------------
#define RS 144
#define MAT_BYTES (128 * RS)
#define STG_BYTES (2 * MAT_BYTES)
#define SMEM_TOT  (2 * STG_BYTES)     // 73728

__device__ __forceinline__ uint32_t smem_u32(const void* p) {
    uint32_t a;
    asm("{ .reg .u64 t; cvta.to.shared.u64 t, %1; cvt.u32.u64 %0, t; }" : "=r"(a) : "l"(p));
    return a;
}

#define CPA16(dst, src) \
    asm volatile("cp.async.cg.shared.global [%0], [%1], 16;" :: "r"(dst), "l"(src))

#define LDM4(r0, r1, r2, r3, a)                                                  \
    asm volatile("ldmatrix.sync.aligned.m8n8.x4.shared.b16 {%0,%1,%2,%3}, [%4];" \
                 : "=r"(r0), "=r"(r1), "=r"(r2), "=r"(r3) : "r"(a))

#define MMA(d, a, b0v, b1v)                                                      \
    asm volatile("mma.sync.aligned.m16n8k16.row.col.f32.f16.f16.f32 "            \
                 "{%0,%1,%2,%3}, {%4,%5,%6,%7}, {%8,%9}, {%0,%1,%2,%3};"         \
                 : "+f"((d)[0]), "+f"((d)[1]), "+f"((d)[2]), "+f"((d)[3])        \
                 : "r"((a)[0]), "r"((a)[1]), "r"((a)[2]), "r"((a)[3]),           \
                   "r"(b0v), "r"(b1v))

__device__ __forceinline__ float2 wred(float a, float b) {
    #pragma unroll
    for (int o = 16; o > 0; o >>= 1) {
        a += __shfl_xor_sync(0xffffffffu, a, o);
        b += __shfl_xor_sync(0xffffffffu, b, o);
    }
    return make_float2(a, b);
}

__global__ void __launch_bounds__(256, 2) k_moe(const float* __restrict__ b1,
                                                const float* __restrict__ b2,
                                                const float* __restrict__ x,
                                                const int* __restrict__ ts,
                                                const float* __restrict__ W2,
                                                const float* __restrict__ ln_g,
                                                const float* __restrict__ ln_b,
                                                const float* __restrict__ og,
                                                const float* __restrict__ ob,
                                                float* __restrict__ out) {
    extern __shared__ __align__(16) char smem[];
    __shared__ int s_idx;
    __shared__ int s_row[128];
    const uint32_t sb = smem_u32(smem);

    const int t = threadIdx.x;
    const int wid = t >> 5;
    const int lane = t & 31;
    const int wm = wid & 3;
    const int wn = wid >> 2;
    const int rr0 = t >> 3;
    const int cc0 = t & 7;
    const uint32_t aoff = (uint32_t)(lane & 15) * RS + (lane >> 4) * 16;
    const uint32_t boff = (uint32_t)((lane & 7) + (lane >> 4) * 8) * RS + ((lane >> 3) & 1) * 16;
    const int g = lane >> 2, q = lane & 3;

    for (;;) {
        __syncthreads();   // protect s_idx / s_row / smem reuse across tiles
        if (t == 0) s_idx = atomicAdd(&g_tile, 1);
        __syncthreads();
        const int idx = s_idx;
        if (idx >= g_total) break;

        // ================= W2 conversion strips =================
        if (idx < NW2) {
            int e = idx / 12;
            int nb = (idx % 12) * 64;
            float (*tile)[65] = (float(*)[65])smem;
            for (int kb = 0; kb < FF / 64; kb++)
                convW_body(W2, g_W2h, FF, HD, e, nb, kb * 64, tile);
            __threadfence();
            __syncthreads();
            if (t == 0) atomicAdd(&g_cv2, 1);
            continue;
        }

        // ================= zero-LN tiles =================
        if (idx < QHEAD) {
            const int base = (idx - NW2) * 128;
            #pragma unroll 1
            for (int i = 0; i < 16; i++) {
                int tok = base + wid * 16 + i;
                if (ts[tok] != 0) continue;
                const float4* xr = (const float4*)(x + (size_t)tok * HD);
                float4 xv[6];
                float s = 0.f, s2 = 0.f;
                #pragma unroll
                for (int j = 0; j < 6; j++) {
                    float4 v = xr[lane + 32 * j];
                    xv[j] = v;
                    s += v.x + v.y + v.z + v.w;
                    s2 += v.x * v.x + v.y * v.y + v.z * v.z + v.w * v.w;
                }
                float2 r = wred(s, s2);
                float m = r.x * (1.f / (float)HD);
                float var = r.y * (1.f / (float)HD) - m * m;
                float inv = rsqrtf(fmaxf(var, 0.f) + 1e-12f);
                float4* outr = (float4*)(out + (size_t)tok * HD);
                #pragma unroll
                for (int j = 0; j < 6; j++) {
                    int ci = lane + 32 * j;
                    float4 gv = ((const float4*)og)[ci];
                    float4 bv = ((const float4*)ob)[ci];
                    float4 ov;
                    ov.x = (xv[j].x - m) * inv * gv.x + bv.x;
                    ov.y = (xv[j].y - m) * inv * gv.y + bv.y;
                    ov.z = (xv[j].z - m) * inv * gv.z + bv.z;
                    ov.w = (xv[j].w - m) * inv * gv.w + bv.w;
                    outr[ci] = ov;
                }
            }
            continue;
        }

        const int e1 = g_e1, e2 = g_e2;

        // ================= expert-LN tiles =================
        if (idx >= e2) {
            const int b = idx - e2;
            int e = 0;
            #pragma unroll
            for (int qq = 1; qq < NE; qq++) if (b >= g_yoff[qq]) e = qq;
            const int y = b - g_yoff[e];
            const int cnt = g_counts[e];
            const int row0 = y * 128;

            if (t == 0) {
                while (atomicAdd(&g_done2[e * MAXB + y], 0) < NX2) __nanosleep(256);
            }
            __syncthreads();
            __threadfence();

            #pragma unroll 1
            for (int i = 0; i < 16; i++) {
                int r = row0 + wid * 16 + i;
                if (r >= cnt) continue;
                int tok = g_idx[e * NTOK + r];
                const float4* xr = (const float4*)(x + (size_t)tok * HD);
                const float4* yr = (const float4*)(g_Y + ((size_t)e * NTOK + r) * HD);
                float4 xv[6], yv[6];
                float s = 0.f, s2 = 0.f;
                #pragma unroll
                for (int j = 0; j < 6; j++) {
                    float4 a = xr[lane + 32 * j];
                    float4 v = yr[lane + 32 * j];
                    v.x += a.x; v.y += a.y; v.z += a.z; v.w += a.w;
                    xv[j] = a; yv[j] = v;
                    s += v.x + v.y + v.z + v.w;
                    s2 += v.x * v.x + v.y * v.y + v.z * v.z + v.w * v.w;
                }
                float2 rr = wred(s, s2);
                float m = rr.x * (1.f / (float)HD);
                float var = rr.y * (1.f / (float)HD) - m * m;
                float inv = rsqrtf(fmaxf(var, 0.f) + 1e-12f);
                float s3 = 0.f, s4 = 0.f;
                float4 zv[6];
                #pragma unroll
                for (int j = 0; j < 6; j++) {
                    int ci = lane + 32 * j;
                    float4 gv = ((const float4*)(ln_g + e * HD))[ci];
                    float4 bv = ((const float4*)(ln_b + e * HD))[ci];
                    float4 z;
                    z.x = (yv[j].x - m) * inv * gv.x + bv.x + xv[j].x;
                    z.y = (yv[j].y - m) * inv * gv.y + bv.y + xv[j].y;
                    z.z = (yv[j].z - m) * inv * gv.z + bv.z + xv[j].z;
                    z.w = (yv[j].w - m) * inv * gv.w + bv.w + xv[j].w;
                    zv[j] = z;
                    s3 += z.x + z.y + z.z + z.w;
                    s4 += z.x * z.x + z.y * z.y + z.z * z.z + z.w * z.w;
                }
                float2 r2 = wred(s3, s4);
                float m2 = r2.x * (1.f / (float)HD);
                float var2 = r2.y * (1.f / (float)HD) - m2 * m2;
                float inv2 = rsqrtf(fmaxf(var2, 0.f) + 1e-12f);
                float4* outr = (float4*)(out + (size_t)tok * HD);
                #pragma unroll
                for (int j = 0; j < 6; j++) {
                    int ci = lane + 32 * j;
                    float4 gv = ((const float4*)og)[ci];
                    float4 bv = ((const float4*)ob)[ci];
                    float4 ov;
                    ov.x = (zv[j].x - m2) * inv2 * gv.x + bv.x;
                    ov.y = (zv[j].y - m2) * inv2 * gv.y + bv.y;
                    ov.z = (zv[j].z - m2) * inv2 * gv.z + bv.z;
                    ov.w = (zv[j].w - m2) * inv2 * gv.w + bv.w;
                    outr[ci] = ov;
                }
            }
            continue;
        }

        // ================= GEMM tiles =================
        int layer, xb, b;
        if (idx < e1) { layer = 1; int j = idx - QHEAD; xb = j % NX1; b = j / NX1; }
        else          { layer = 2; int j = idx - e1;    xb = j % NX2; b = j / NX2; }
        int e = 0;
        #pragma unroll
        for (int qq = 1; qq < NE; qq++) if (b >= g_yoff[qq]) e = qq;
        const int y = b - g_yoff[e];
        const int cnt = g_counts[e];
        const int row0 = y * 128;
        const int n0 = xb * 128;

        const uint4* pA;
        const uint4* pB;
        const float* bias;
        int KT, NTOT;
        if (layer == 1) {
            pA = (const uint4*)g_xh;  pB = (const uint4*)g_W1h;
            bias = b1; KT = HD; NTOT = FF;
        } else {
            pA = (const uint4*)g_Hh;  pB = (const uint4*)g_W2h;
            bias = b2; KT = FF; NTOT = HD;
        }
        const int C = KT / 64;
        const int KU4 = KT / 8;

        if (layer == 2) {
            if (t == 0) {
                while (atomicAdd(&g_cv2, 0) < NW2) __nanosleep(128);
                while (atomicAdd(&g_done[e * MAXB + y], 0) < NX1) __nanosleep(256);
            }
            __syncthreads();
            __threadfence();
        }

        if (t < 128) {
            int r = row0 + t;
            if (layer == 1)
                s_row[t] = (r < cnt) ? g_idx[e * NTOK + r] : g_idx[e * NTOK];
            else
                s_row[t] = e * NTOK + r;
        }
        __syncthreads();

        pB += ((size_t)e * NTOT + n0) * (size_t)KU4;

        auto load_stage = [&](int s, int c) {
            const uint32_t st = sb + s * STG_BYTES;
            const int k4 = c * 8;
            #pragma unroll
            for (int it = 0; it < 4; ++it) {
                int row = rr0 + it * 32;
                uint32_t so = (uint32_t)row * RS + cc0 * 16;
                CPA16(st + so, pA + (size_t)s_row[row] * KU4 + k4 + cc0);
                CPA16(st + MAT_BYTES + so, pB + (size_t)row * KU4 + k4 + cc0);
            }
            asm volatile("cp.async.commit_group;" ::: "memory");
        };

        float acc[2][8][4];
        #pragma unroll
        for (int mi = 0; mi < 2; mi++)
            #pragma unroll
            for (int ni = 0; ni < 8; ni++)
                #pragma unroll
                for (int k = 0; k < 4; k++) acc[mi][ni][k] = 0.f;

        load_stage(0, 0);

        for (int c = 0; c < C; ++c) {
            if (c + 1 < C) {
                load_stage((c + 1) & 1, c + 1);
                asm volatile("cp.async.wait_group 1;" ::: "memory");
            } else {
                asm volatile("cp.async.wait_group 0;" ::: "memory");
            }
            __syncthreads();

            const uint32_t bAh = sb + (c & 1) * STG_BYTES;
            const uint32_t bBh = bAh + MAT_BYTES;

            #pragma unroll
            for (int ks = 0; ks < 64; ks += 16) {
                uint32_t ah[2][4];
                #pragma unroll
                for (int mi = 0; mi < 2; mi++) {
                    uint32_t ab = (uint32_t)(wm * 32 + mi * 16) * RS + ks * 2 + aoff;
                    LDM4(ah[mi][0], ah[mi][1], ah[mi][2], ah[mi][3], bAh + ab);
                }
                #pragma unroll
                for (int ng = 0; ng < 4; ng++) {
                    uint32_t bb = (uint32_t)(wn * 64 + ng * 16) * RS + ks * 2 + boff;
                    uint32_t bh[4];
                    LDM4(bh[0], bh[1], bh[2], bh[3], bBh + bb);
                    #pragma unroll
                    for (int mi = 0; mi < 2; mi++) {
                        MMA(acc[mi][ng * 2],     ah[mi], bh[0], bh[1]);
                        MMA(acc[mi][ng * 2 + 1], ah[mi], bh[2], bh[3]);
                    }
                }
            }
            __syncthreads();
        }

        #pragma unroll
        for (int mi = 0; mi < 2; mi++) {
            #pragma unroll
            for (int half = 0; half < 2; half++) {
                int r = row0 + wm * 32 + mi * 16 + g + half * 8;
                if (r >= cnt) continue;
                size_t rb = ((size_t)e * NTOK + r) * (size_t)NTOT;
                #pragma unroll
                for (int ni = 0; ni < 8; ni++) {
                    int col = n0 + wn * 64 + ni * 8 + q * 2;
                    float v0 = acc[mi][ni][half * 2 + 0] + bias[e * NTOT + col];
                    float v1 = acc[mi][ni][half * 2 + 1] + bias[e * NTOT + col + 1];
                    if (layer == 1) {
                        v0 = 0.5f * v0 * (1.f + erff(v0 * 0.70710678118654752f));
                        v1 = 0.5f * v1 * (1.f + erff(v1 * 0.70710678118654752f));
                        __half h0 = __float2half(v0);
                        __half h1 = __float2half(v1);
                        uint32_t hw = (uint32_t)__half_as_ushort(h0) |
                                      ((uint32_t)__half_as_ushort(h1) << 16);
                        *(uint32_t*)(g_Hh + rb + col) = hw;
                    } else {
                        float2 v;
                        v.x = v0; v.y = v1;
                        *(float2*)(g_Y + rb + col) = v;
                    }
                }
            }
        }

        __threadfence();
        __syncthreads();
        if (t == 0) {
            if (layer == 1) atomicAdd(&g_done[e * MAXB + y], 1);
            else            atomicAdd(&g_done2[e * MAXB + y], 1);
        }
    }
}

// ---------------- launch ----------------
extern "C" void kernel_launch(void* const* d_in, const int* in_sizes, int n_in,
                              void* d_out, int out_size) {
    const float* x    = (const float*)d_in[0];
    const int*   ts   = (const int*)  d_in[1];
    const float* W1   = (const float*)d_in[2];
    const float* b1   = (const float*)d_in[3];
    const float* W2   = (const float*)d_in[4];
    const float* b2   = (const float*)d_in[5];
    const float* ln_g = (const float*)d_in[6];
    const float* ln_b = (const float*)d_in[7];
    const float* og   = (const float*)d_in[8];
    const float* ob   = (const float*)d_in[9];
    float* out = (float*)d_out;

    cudaFuncSetAttribute(k_moe, cudaFuncAttributeMaxDynamicSharedMemorySize, SMEM_TOT);

    k_zero<<<1, 32>>>();
    k_build<<<NTOK / 256, 256>>>(ts);
    k_prep<<<1, 256>>>();
    k_conv<<<NBX + NBW1, 256>>>(x, W1);
    k_moe<<<GRID_PERSIST, 256, SMEM_TOT>>>(b1, b2, x, ts, W2,
                                           ln_g, ln_b, og, ob, out);
}

// round 16
// speedup vs baseline: 1.0603x; 1.0603x over previous
#include <cuda_runtime.h>
#include <cuda_fp16.h>
#include <math.h>
#include <stdint.h>

#define NTOK 16384
#define HD 768
#define FF 3072
#define NE 4
#define NX1 (FF / 128)     // 24 layer-1 col blocks
#define NX2 (HD / 128)     // 6  layer-2 col blocks
#define MAXB (NTOK / 128)  // 128 max row blocks per expert
#define NZT  (NTOK / 128)  // 128 zero-LN tiles
#define GRID_PERSIST 304

// ---------------- device scratch (no allocations allowed) ----------------
__device__ int g_counts[NE];
__device__ int g_idx[NE * NTOK];
__device__ int g_yoff[NE + 1];
__device__ int g_e1;       // end of layer-1 range  (NZT + T1)
__device__ int g_e2;       // end of layer-2 range  (g_e1 + T2)
__device__ int g_total;    // g_e2 + nrowblocks (expert-LN tiles)
__device__ int g_tile;
__device__ int g_done[NE * MAXB];
__device__ int g_done2[NE * MAXB];
__device__ __half g_xh[(size_t)NTOK * HD];       // x in fp16, token order
__device__ __half g_W1h[(size_t)NE * FF * HD];   // [e][n(FF)][k(HD)] fp16
__device__ __half g_W2h[(size_t)NE * HD * FF];   // [e][n(HD)][k(FF)] fp16
__device__ __half g_Hh[(size_t)NE * NTOK * FF];
__device__ float g_Y[(size_t)NE * NTOK * HD];

// ---------------- small kernels ----------------
__global__ void k_zero() {
    if (threadIdx.x < NE) g_counts[threadIdx.x] = 0;
}

__global__ void k_build(const int* __restrict__ ts) {
    int t = blockIdx.x * blockDim.x + threadIdx.x;
    if (t < NTOK) {
        int e = ts[t];
        if (e > 0) {
            int s = atomicAdd(&g_counts[e - 1], 1);
            g_idx[(e - 1) * NTOK + s] = t;
        }
    }
}

__global__ void k_prep() {
    __shared__ int nyb[NE];
    int t = threadIdx.x;
    if (t < NE) nyb[t] = (g_counts[t] + 127) >> 7;
    __syncthreads();
    if (t == 0) {
        int off = 0;
        for (int e = 0; e < NE; e++) { g_yoff[e] = off; off += nyb[e]; }
        g_yoff[NE] = off;
        g_e1 = NZT + off * NX1;
        g_e2 = NZT + off * (NX1 + NX2);
        g_total = NZT + off * (NX1 + NX2 + 1);
        g_tile = 0;
    }
    for (int i = t; i < NE * MAXB; i += blockDim.x) {
        g_done[i] = 0;
        g_done2[i] = 0;
    }
}

// ---------------- merged conversion kernel ----------------
// blocks [0, 6144):             x fp32 -> fp16 (8 elems/thread)
// blocks [6144, 6144+2304):     W1 transpose+convert (64x64 tiles)
// blocks [6144+2304, +2304):    W2 transpose+convert
#define NBX 6144
#define NBW 2304

__device__ __forceinline__ void convW_body(const float* __restrict__ W, __half* O,
                                           int K, int N, int e, int nb, int kb,
                                           float (*tile)[65]) {
    const int tx = threadIdx.x & 63;
    const int ty = threadIdx.x >> 6;
    const float* src = W + ((size_t)e * K + kb) * N + nb;
    #pragma unroll
    for (int j = 0; j < 16; j++) {
        int r = ty + j * 4;
        tile[r][tx] = src[(size_t)r * N + tx];
    }
    __syncthreads();
    __half* dst = O + ((size_t)e * N + nb) * K + kb;
    #pragma unroll
    for (int j = 0; j < 16; j++) {
        int rr = ty + j * 4;
        dst[(size_t)rr * K + tx] = __float2half(tile[tx][rr]);
    }
}

__global__ void __launch_bounds__(256) k_conv(const float* __restrict__ x,
                                              const float* __restrict__ W1,
                                              const float* __restrict__ W2) {
    __shared__ float tile[64][65];
    const int bid = blockIdx.x;
    if (bid < NBX) {
        size_t i = ((size_t)bid * 256 + threadIdx.x) * 8;
        float4 a = *(const float4*)(x + i);
        float4 b = *(const float4*)(x + i + 4);
        __half2 h0 = __floats2half2_rn(a.x, a.y);
        __half2 h1 = __floats2half2_rn(a.z, a.w);
        __half2 h2 = __floats2half2_rn(b.x, b.y);
        __half2 h3 = __floats2half2_rn(b.z, b.w);
        uint4 v;
        v.x = *(uint32_t*)&h0;
        v.y = *(uint32_t*)&h1;
        v.z = *(uint32_t*)&h2;
        v.w = *(uint32_t*)&h3;
        *(uint4*)(g_xh + i) = v;
    } else if (bid < NBX + NBW) {
        int b = bid - NBX;                    // W1: K=HD, N=FF; tiles 48 x 12
        int xb = b % (FF / 64);
        int yb = (b / (FF / 64)) % (HD / 64);
        int e = b / ((FF / 64) * (HD / 64));
        convW_body(W1, g_W1h, HD, FF, e, xb * 64, yb * 64, tile);
    } else {
        int b = bid - NBX - NBW;              // W2: K=FF, N=HD; tiles 12 x 48
        int xb = b % (HD / 64);
        int yb = (b / (HD / 64)) % (FF / 64);
        int e = b / ((HD / 64) * (FF / 64));
        convW_body(W2, g_W2h, FF, HD, e, xb * 64, yb * 64, tile);
    }
}

// ---------------- persistent fused kernel: GEMM1 + GEMM2 + LN ----------------
#define RS 144
#define MAT_BYTES (128 * RS)
#define STG_BYTES (2 * MAT_BYTES)
#define SMEM_TOT  (2 * STG_BYTES)     // 73728

__device__ __forceinline__ uint32_t smem_u32(const void* p) {
    uint32_t a;
    asm("{ .reg .u64 t; cvta.to.shared.u64 t, %1; cvt.u32.u64 %0, t; }" : "=r"(a) : "l"(p));
    return a;
}

#define CPA16(dst, src) \
    asm volatile("cp.async.cg.shared.global [%0], [%1], 16;" :: "r"(dst), "l"(src))

#define LDM4(r0, r1, r2, r3, a)                                                  \
    asm volatile("ldmatrix.sync.aligned.m8n8.x4.shared.b16 {%0,%1,%2,%3}, [%4];" \
                 : "=r"(r0), "=r"(r1), "=r"(r2), "=r"(r3) : "r"(a))

#define MMA(d, a, b0v, b1v)                                                      \
    asm volatile("mma.sync.aligned.m16n8k16.row.col.f32.f16.f16.f32 "            \
                 "{%0,%1,%2,%3}, {%4,%5,%6,%7}, {%8,%9}, {%0,%1,%2,%3};"         \
                 : "+f"((d)[0]), "+f"((d)[1]), "+f"((d)[2]), "+f"((d)[3])        \
                 : "r"((a)[0]), "r"((a)[1]), "r"((a)[2]), "r"((a)[3]),           \
                   "r"(b0v), "r"(b1v))

__device__ __forceinline__ float2 wred(float a, float b) {
    #pragma unroll
    for (int o = 16; o > 0; o >>= 1) {
        a += __shfl_xor_sync(0xffffffffu, a, o);
        b += __shfl_xor_sync(0xffffffffu, b, o);
    }
    return make_float2(a, b);
}

__global__ void __launch_bounds__(256, 2) k_moe(const float* __restrict__ b1,
                                                const float* __restrict__ b2,
                                                const float* __restrict__ x,
                                                const int* __restrict__ ts,
                                                const float* __restrict__ ln_g,
                                                const float* __restrict__ ln_b,
                                                const float* __restrict__ og,
                                                const float* __restrict__ ob,
                                                float* __restrict__ out) {
    extern __shared__ __align__(16) char smem[];
    __shared__ int s_idx;
    __shared__ int s_row[128];
    const uint32_t sb = smem_u32(smem);

    const int t = threadIdx.x;
    const int wid = t >> 5;
    const int lane = t & 31;
    const int wm = wid & 3;
    const int wn = wid >> 2;
    const int rr0 = t >> 3;
    const int cc0 = t & 7;
    const uint32_t aoff = (uint32_t)(lane & 15) * RS + (lane >> 4) * 16;
    const uint32_t boff = (uint32_t)((lane & 7) + (lane >> 4) * 8) * RS + ((lane >> 3) & 1) * 16;
    const int g = lane >> 2, q = lane & 3;

    for (;;) {
        __syncthreads();   // protect s_idx / s_row / smem reuse across tiles
        if (t == 0) s_idx = atomicAdd(&g_tile, 1);
        __syncthreads();
        const int idx = s_idx;
        if (idx >= g_total) break;

        // ================= zero-LN tiles =================
        if (idx < NZT) {
            const int base = idx * 128;
            #pragma unroll 1
            for (int i = 0; i < 16; i++) {
                int tok = base + wid * 16 + i;
                if (ts[tok] != 0) continue;
                const float4* xr = (const float4*)(x + (size_t)tok * HD);
                float4 xv[6];
                float s = 0.f, s2 = 0.f;
                #pragma unroll
                for (int j = 0; j < 6; j++) {
                    float4 v = xr[lane + 32 * j];
                    xv[j] = v;
                    s += v.x + v.y + v.z + v.w;
                    s2 += v.x * v.x + v.y * v.y + v.z * v.z + v.w * v.w;
                }
                float2 r = wred(s, s2);
                float m = r.x * (1.f / (float)HD);
                float var = r.y * (1.f / (float)HD) - m * m;
                float inv = rsqrtf(fmaxf(var, 0.f) + 1e-12f);
                float4* outr = (float4*)(out + (size_t)tok * HD);
                #pragma unroll
                for (int j = 0; j < 6; j++) {
                    int ci = lane + 32 * j;
                    float4 gv = ((const float4*)og)[ci];
                    float4 bv = ((const float4*)ob)[ci];
                    float4 ov;
                    ov.x = (xv[j].x - m) * inv * gv.x + bv.x;
                    ov.y = (xv[j].y - m) * inv * gv.y + bv.y;
                    ov.z = (xv[j].z - m) * inv * gv.z + bv.z;
                    ov.w = (xv[j].w - m) * inv * gv.w + bv.w;
                    outr[ci] = ov;
                }
            }
            continue;
        }

        const int e1 = g_e1, e2 = g_e2;

        // ================= expert-LN tiles =================
        if (idx >= e2) {
            const int b = idx - e2;
            int e = 0;
            #pragma unroll
            for (int qq = 1; qq < NE; qq++) if (b >= g_yoff[qq]) e = qq;
            const int y = b - g_yoff[e];
            const int cnt = g_counts[e];
            const int row0 = y * 128;

            if (t == 0) {
                while (atomicAdd(&g_done2[e * MAXB + y], 0) < NX2) __nanosleep(256);
            }
            __syncthreads();
            __threadfence();

            #pragma unroll 1
            for (int i = 0; i < 16; i++) {
                int r = row0 + wid * 16 + i;
                if (r >= cnt) continue;
                int tok = g_idx[e * NTOK + r];
                const float4* xr = (const float4*)(x + (size_t)tok * HD);
                const float4* yr = (const float4*)(g_Y + ((size_t)e * NTOK + r) * HD);
                float4 xv[6], yv[6];
                float s = 0.f, s2 = 0.f;
                #pragma unroll
                for (int j = 0; j < 6; j++) {
                    float4 a = xr[lane + 32 * j];
                    float4 v = yr[lane + 32 * j];
                    v.x += a.x; v.y += a.y; v.z += a.z; v.w += a.w;
                    xv[j] = a; yv[j] = v;
                    s += v.x + v.y + v.z + v.w;
                    s2 += v.x * v.x + v.y * v.y + v.z * v.z + v.w * v.w;
                }
                float2 rr = wred(s, s2);
                float m = rr.x * (1.f / (float)HD);
                float var = rr.y * (1.f / (float)HD) - m * m;
                float inv = rsqrtf(fmaxf(var, 0.f) + 1e-12f);
                float s3 = 0.f, s4 = 0.f;
                float4 zv[6];
                #pragma unroll
                for (int j = 0; j < 6; j++) {
                    int ci = lane + 32 * j;
                    float4 gv = ((const float4*)(ln_g + e * HD))[ci];
                    float4 bv = ((const float4*)(ln_b + e * HD))[ci];
                    float4 z;
                    z.x = (yv[j].x - m) * inv * gv.x + bv.x + xv[j].x;
                    z.y = (yv[j].y - m) * inv * gv.y + bv.y + xv[j].y;
                    z.z = (yv[j].z - m) * inv * gv.z + bv.z + xv[j].z;
                    z.w = (yv[j].w - m) * inv * gv.w + bv.w + xv[j].w;
                    zv[j] = z;
                    s3 += z.x + z.y + z.z + z.w;
                    s4 += z.x * z.x + z.y * z.y + z.z * z.z + z.w * z.w;
                }
                float2 r2 = wred(s3, s4);
                float m2 = r2.x * (1.f / (float)HD);
                float var2 = r2.y * (1.f / (float)HD) - m2 * m2;
                float inv2 = rsqrtf(fmaxf(var2, 0.f) + 1e-12f);
                float4* outr = (float4*)(out + (size_t)tok * HD);
                #pragma unroll
                for (int j = 0; j < 6; j++) {
                    int ci = lane + 32 * j;
                    float4 gv = ((const float4*)og)[ci];
                    float4 bv = ((const float4*)ob)[ci];
                    float4 ov;
                    ov.x = (zv[j].x - m2) * inv2 * gv.x + bv.x;
                    ov.y = (zv[j].y - m2) * inv2 * gv.y + bv.y;
                    ov.z = (zv[j].z - m2) * inv2 * gv.z + bv.z;
                    ov.w = (zv[j].w - m2) * inv2 * gv.w + bv.w;
                    outr[ci] = ov;
                }
            }
            continue;
        }

        // ================= GEMM tiles =================
        int layer, xb, b;
        if (idx < e1) { layer = 1; int j = idx - NZT; xb = j % NX1; b = j / NX1; }
        else          { layer = 2; int j = idx - e1;  xb = j % NX2; b = j / NX2; }
        int e = 0;
        #pragma unroll
        for (int qq = 1; qq < NE; qq++) if (b >= g_yoff[qq]) e = qq;
        const int y = b - g_yoff[e];
        const int cnt = g_counts[e];
        const int row0 = y * 128;
        const int n0 = xb * 128;

        const uint4* pA;
        const uint4* pB;
        const float* bias;
        int KT, NTOT;
        if (layer == 1) {
            pA = (const uint4*)g_xh;  pB = (const uint4*)g_W1h;
            bias = b1; KT = HD; NTOT = FF;
        } else {
            pA = (const uint4*)g_Hh;  pB = (const uint4*)g_W2h;
            bias = b2; KT = FF; NTOT = HD;
        }
        const int C = KT / 64;
        const int KU4 = KT / 8;

        if (layer == 2) {
            if (t == 0) {
                while (atomicAdd(&g_done[e * MAXB + y], 0) < NX1) __nanosleep(256);
            }
            __syncthreads();
            __threadfence();
        }

        if (t < 128) {
            int r = row0 + t;
            if (layer == 1)
                s_row[t] = (r < cnt) ? g_idx[e * NTOK + r] : g_idx[e * NTOK];
            else
                s_row[t] = e * NTOK + r;
        }
        __syncthreads();

        pB += ((size_t)e * NTOT + n0) * (size_t)KU4;

        auto load_stage = [&](int s, int c) {
            const uint32_t st = sb + s * STG_BYTES;
            const int k4 = c * 8;
            #pragma unroll
            for (int it = 0; it < 4; ++it) {
                int row = rr0 + it * 32;
                uint32_t so = (uint32_t)row * RS + cc0 * 16;
                CPA16(st + so, pA + (size_t)s_row[row] * KU4 + k4 + cc0);
                CPA16(st + MAT_BYTES + so, pB + (size_t)row * KU4 + k4 + cc0);
            }
            asm volatile("cp.async.commit_group;" ::: "memory");
        };

        float acc[2][8][4];
        #pragma unroll
        for (int mi = 0; mi < 2; mi++)
            #pragma unroll
            for (int ni = 0; ni < 8; ni++)
                #pragma unroll
                for (int k = 0; k < 4; k++) acc[mi][ni][k] = 0.f;

        load_stage(0, 0);

        for (int c = 0; c < C; ++c) {
            if (c + 1 < C) {
                load_stage((c + 1) & 1, c + 1);
                asm volatile("cp.async.wait_group 1;" ::: "memory");
            } else {
                asm volatile("cp.async.wait_group 0;" ::: "memory");
            }
            __syncthreads();

            const uint32_t bAh = sb + (c & 1) * STG_BYTES;
            const uint32_t bBh = bAh + MAT_BYTES;

            #pragma unroll
            for (int ks = 0; ks < 64; ks += 16) {
                uint32_t ah[2][4];
                #pragma unroll
                for (int mi = 0; mi < 2; mi++) {
                    uint32_t ab = (uint32_t)(wm * 32 + mi * 16) * RS + ks * 2 + aoff;
                    LDM4(ah[mi][0], ah[mi][1], ah[mi][2], ah[mi][3], bAh + ab);
                }
                #pragma unroll
                for (int ng = 0; ng < 4; ng++) {
                    uint32_t bb = (uint32_t)(wn * 64 + ng * 16) * RS + ks * 2 + boff;
                    uint32_t bh[4];
                    LDM4(bh[0], bh[1], bh[2], bh[3], bBh + bb);
                    #pragma unroll
                    for (int mi = 0; mi < 2; mi++) {
                        MMA(acc[mi][ng * 2],     ah[mi], bh[0], bh[1]);
                        MMA(acc[mi][ng * 2 + 1], ah[mi], bh[2], bh[3]);
                    }
                }
            }
            __syncthreads();
        }

        #pragma unroll
        for (int mi = 0; mi < 2; mi++) {
            #pragma unroll
            for (int half = 0; half < 2; half++) {
                int r = row0 + wm * 32 + mi * 16 + g + half * 8;
                if (r >= cnt) continue;
                size_t rb = ((size_t)e * NTOK + r) * (size_t)NTOT;
                #pragma unroll
                for (int ni = 0; ni < 8; ni++) {
                    int col = n0 + wn * 64 + ni * 8 + q * 2;
                    float v0 = acc[mi][ni][half * 2 + 0] + bias[e * NTOT + col];
                    float v1 = acc[mi][ni][half * 2 + 1] + bias[e * NTOT + col + 1];
                    if (layer == 1) {
                        v0 = 0.5f * v0 * (1.f + erff(v0 * 0.70710678118654752f));
                        v1 = 0.5f * v1 * (1.f + erff(v1 * 0.70710678118654752f));
                        __half h0 = __float2half(v0);
                        __half h1 = __float2half(v1);
                        uint32_t hw = (uint32_t)__half_as_ushort(h0) |
                                      ((uint32_t)__half_as_ushort(h1) << 16);
                        *(uint32_t*)(g_Hh + rb + col) = hw;
                    } else {
                        float2 v;
                        v.x = v0; v.y = v1;
                        *(float2*)(g_Y + rb + col) = v;
                    }
                }
            }
        }

        __threadfence();
        __syncthreads();
        if (t == 0) {
            if (layer == 1) atomicAdd(&g_done[e * MAXB + y], 1);
            else            atomicAdd(&g_done2[e * MAXB + y], 1);
        }
    }
}

// ---------------- launch ----------------
extern "C" void kernel_launch(void* const* d_in, const int* in_sizes, int n_in,
                              void* d_out, int out_size) {
    const float* x    = (const float*)d_in[0];
    const int*   ts   = (const int*)  d_in[1];
    const float* W1   = (const float*)d_in[2];
    const float* b1   = (const float*)d_in[3];
    const float* W2   = (const float*)d_in[4];
    const float* b2   = (const float*)d_in[5];
    const float* ln_g = (const float*)d_in[6];
    const float* ln_b = (const float*)d_in[7];
    const float* og   = (const float*)d_in[8];
    const float* ob   = (const float*)d_in[9];
    float* out = (float*)d_out;

    cudaFuncSetAttribute(k_moe, cudaFuncAttributeMaxDynamicSharedMemorySize, SMEM_TOT);

    k_zero<<<1, 32>>>();
    k_build<<<NTOK / 256, 256>>>(ts);
    k_prep<<<1, 256>>>();
    k_conv<<<NBX + 2 * NBW, 256>>>(x, W1, W2);
    k_moe<<<GRID_PERSIST, 256, SMEM_TOT>>>(b1, b2, x, ts, ln_g, ln_b, og, ob, out);
}